// round 16
// baseline (speedup 1.0000x reference)
#include <cuda_runtime.h>
#include <cuda_fp16.h>
#include <math.h>
#include <cstdint>

// ===========================================================================
// Fused MLP on HMMA fp16 (hard dispatch rate 512 MAC/cyc/SM), bulk-copy
// staged; all GEMM operands in gmem as exact padded smem tile images.
//   prep   : (merged) x fp32 -> fp16 64-K 144-layout A-blocks + stats proj;
//            W1/W2 -> 144-layout 64-K B-blocks; W3 -> 272 blocks; Wc1T fp16
//   gemm1  : h1 = relu(x@W1+b1), K-chunk 64, 110.6KB smem -> 2 CTAs/SM
//   megatail: full-width gemm2 -> smem h2 -> gemm3 -> C1 -> C2/C3 -> sigmoid
// ===========================================================================

#define MTOT 65536
#define ABLK 34816u      // 128 rows x 272B
#define ABLK64 18432u    // 128 rows x 144B
#define BBLK64 36864u    // 256 rows x 144B

// ---------------- device scratch -------------------------------------------
__device__ __half g_x [(size_t)512 * 6 * 9216];    // x: [mt][kb(6)] 128r x 144B
__device__ __half g_w1[(size_t)2 * 6 * 18432];     // w1: [pass(2)][kb(6)] 256r x 144B
__device__ __half g_w2[(size_t)8 * 18432];         // w2: [kb(8)] 256r x 144B
__device__ __half g_w3[(size_t)2 * 17408];         // w3: 2 x 128r x 272B
__device__ __half g_h1[(size_t)512 * 8 * 9216];    // h1: per-tile 8 x 64-K (144)
__device__ __half g_wc1t[64 * 160];
__device__ __half g_statproj[(size_t)MTOT * 32];

// ---------------- helpers --------------------------------------------------
__device__ __forceinline__ uint32_t smem_to_u32(const void* p) {
    uint32_t a;
    asm("{ .reg .u64 t; cvta.to.shared.u64 t, %1; cvt.u32.u64 %0, t; }"
        : "=r"(a) : "l"(p));
    return a;
}
__device__ __forceinline__ void ldsm4(uint32_t* r, uint32_t addr) {
    asm volatile("ldmatrix.sync.aligned.m8n8.x4.shared.b16 {%0,%1,%2,%3}, [%4];"
        : "=r"(r[0]), "=r"(r[1]), "=r"(r[2]), "=r"(r[3]) : "r"(addr));
}
__device__ __forceinline__ void mma16816(float* c, const uint32_t* a,
                                         const uint32_t* b) {
    asm volatile(
        "mma.sync.aligned.m16n8k16.row.col.f32.f16.f16.f32 "
        "{%0,%1,%2,%3}, {%4,%5,%6,%7}, {%8,%9}, {%0,%1,%2,%3};"
        : "+f"(c[0]), "+f"(c[1]), "+f"(c[2]), "+f"(c[3])
        : "r"(a[0]), "r"(a[1]), "r"(a[2]), "r"(a[3]), "r"(b[0]), "r"(b[1]));
}
__device__ __forceinline__ void cp_async16(uint32_t dst, const void* src) {
    asm volatile("cp.async.cg.shared.global [%0], [%1], 16;"
        :: "r"(dst), "l"(src));
}
#define CP_COMMIT() asm volatile("cp.async.commit_group;" ::: "memory")
#define CP_WAIT(n)  asm volatile("cp.async.wait_group %0;" :: "n"(n) : "memory")

__device__ __forceinline__ void bulk_g2s(uint32_t dst, const void* src,
                                         uint32_t bytes, uint32_t mbar) {
    asm volatile(
        "cp.async.bulk.shared::cta.global.mbarrier::complete_tx::bytes "
        "[%0], [%1], %2, [%3];"
        :: "r"(dst), "l"(src), "r"(bytes), "r"(mbar) : "memory");
}
#define MBARRIER_INIT(mbar, cnt) \
    asm volatile("mbarrier.init.shared.b64 [%0], %1;" \
        :: "r"((uint32_t)(mbar)), "r"((uint32_t)(cnt)) : "memory")
#define MBARRIER_EXPECT_TX(mbar, bytes) \
    asm volatile("mbarrier.arrive.expect_tx.shared.b64 _, [%0], %1;" \
        :: "r"((uint32_t)(mbar)), "r"((uint32_t)(bytes)) : "memory")
#define MBARRIER_WAIT_PARITY(mbar, par) do { \
    uint32_t _m = (uint32_t)(mbar); uint32_t _p = (uint32_t)(par); uint32_t _d; \
    asm volatile("{\n\t.reg .pred p;\n\t" \
        "mbarrier.try_wait.parity.acquire.cta.shared::cta.b64 p, [%1], %2;\n\t" \
        "selp.b32 %0, 1, 0, p;\n\t}" : "=r"(_d) : "r"(_m), "r"(_p) : "memory"); \
    if (!_d) { \
        asm volatile("{\n\t.reg .pred P1;\n\t" \
            "WAIT_LOOP_%=:\n\t" \
            "mbarrier.try_wait.parity.acquire.cta.shared::cta.b64 P1, [%0], %1, 0x989680;\n\t" \
            "@P1 bra.uni WAIT_DONE_%=;\n\t" \
            "bra.uni WAIT_LOOP_%=;\n\t" \
            "WAIT_DONE_%=:\n\t}" :: "r"(_m), "r"(_p) : "memory"); \
    } \
} while (0)

__device__ __forceinline__ uint32_t pack_h2(__half a, __half b) {
    __half2 t; t.x = a; t.y = b;
    return *(uint32_t*)&t;
}

// ---------------- merged prep (x part + w part by blockIdx) ----------------
#define XB_BLOCKS (MTOT / 8)                  // 8192
#define W1T_ELEMS (512 * 384)
#define W2T_ELEMS (256 * 512)
#define W3T_ELEMS (128 * 256)
#define WC1T_ELEMS (64 * 160)
#define WT_TOTAL  (W1T_ELEMS + W2T_ELEMS + W3T_ELEMS + WC1T_ELEMS)
#define WB_BLOCKS ((WT_TOTAL + 255) / 256)

__global__ __launch_bounds__(256)
void prep_kernel(const float* __restrict__ x,
                 const float* __restrict__ Ws, const float* __restrict__ bs,
                 const float* __restrict__ W1, const float* __restrict__ W2,
                 const float* __restrict__ W3, const float* __restrict__ Wc1) {
    if (blockIdx.x < XB_BLOCKS) {
        // ---- x role ----
        const int warp = threadIdx.x >> 5, lane = threadIdx.x & 31;
        const int r = blockIdx.x * 8 + warp;
        const float* xr = x + (size_t)r * 365;

        float v[12];
        float s = 0.f, mn = 3.4e38f, mx = -3.4e38f;
#pragma unroll
        for (int i = 0; i < 12; i++) {
            int k = lane + 32 * i;
            bool ok = k < 365;
            v[i] = ok ? xr[k] : 0.f;
            if (ok) { s += v[i]; mn = fminf(mn, v[i]); mx = fmaxf(mx, v[i]); }
        }
#pragma unroll
        for (int o = 16; o; o >>= 1) {
            s += __shfl_xor_sync(0xffffffffu, s, o);
            mn = fminf(mn, __shfl_xor_sync(0xffffffffu, mn, o));
            mx = fmaxf(mx, __shfl_xor_sync(0xffffffffu, mx, o));
        }
        const float mu = s * (1.0f / 365.0f);
        float s2 = 0.f, s3 = 0.f, s4 = 0.f;
#pragma unroll
        for (int i = 0; i < 12; i++) {
            int k = lane + 32 * i;
            if (k < 365) {
                float c = v[i] - mu, c2 = c * c;
                s2 += c2; s3 += c2 * c; s4 += c2 * c2;
            }
        }
#pragma unroll
        for (int o = 16; o; o >>= 1) {
            s2 += __shfl_xor_sync(0xffffffffu, s2, o);
            s3 += __shfl_xor_sync(0xffffffffu, s3, o);
            s4 += __shfl_xor_sync(0xffffffffu, s4, o);
        }
        const float var1 = s2 * (1.0f / 364.0f);
        const float sig = sqrtf(var1);
        const float m3 = s3 * (1.0f / 365.0f);
        const float m4 = s4 * (1.0f / 365.0f);
        const float sig2 = sig * sig;
        const float skew = m3 / (sig * sig2 + 1e-8f);
        const float kurt = m4 / (sig2 * sig2 + 1e-8f);

        {
            const int j = lane;
            float a = bs[j];
            a += mu   * Ws[0 * 32 + j];
            a += sig  * Ws[1 * 32 + j];
            a += mn   * Ws[2 * 32 + j];
            a += mx   * Ws[3 * 32 + j];
            a += skew * Ws[4 * 32 + j];
            a += kurt * Ws[5 * 32 + j];
            g_statproj[(size_t)r * 32 + j] = __float2half_rn(a);
        }
        const int mt = r >> 7, rl = r & 127;
#pragma unroll
        for (int i = 0; i < 12; i++) {
            int k = lane + 32 * i;
            float val = (k < 365) ? v[i] : 0.f;
            const int kb = k >> 6, kl = k & 63;
            g_x[((size_t)(mt * 6 + kb)) * 9216 + rl * 72 + kl] = __float2half_rn(val);
        }
    } else {
        // ---- w role ----
        int idx = (blockIdx.x - XB_BLOCKS) * 256 + threadIdx.x;
        if (idx >= WT_TOTAL) return;
        if (idx < W1T_ELEMS) {
            int n = idx / 384, k = idx % 384;
            float v = (k < 365) ? W1[(size_t)k * 512 + n] : 0.f;
            int pass = n >> 8, nl = n & 255, kb = k >> 6, kl = k & 63;
            g_w1[((size_t)(pass * 6 + kb)) * 18432 + nl * 72 + kl] = __float2half_rn(v);
        } else if (idx < W1T_ELEMS + W2T_ELEMS) {
            int j = idx - W1T_ELEMS;
            int n = j / 512, k = j % 512;
            int kb = k >> 6, kl = k & 63;
            g_w2[(size_t)kb * 18432 + n * 72 + kl] =
                __float2half_rn(W2[(size_t)k * 256 + n]);
        } else if (idx < W1T_ELEMS + W2T_ELEMS + W3T_ELEMS) {
            int j = idx - W1T_ELEMS - W2T_ELEMS;
            int n = j / 256, k = j % 256;
            int kb = k >> 7, kl = k & 127;
            g_w3[(size_t)kb * 17408 + n * 136 + kl] =
                __float2half_rn(W3[(size_t)k * 128 + n]);
        } else {
            int j = idx - W1T_ELEMS - W2T_ELEMS - W3T_ELEMS;
            int n = j / 160, k = j % 160;
            g_wc1t[j] = __float2half_rn(Wc1[(size_t)k * 64 + n]);
        }
    }
}

// ---------------- gemm1: K-chunk 64, 2 CTAs/SM -----------------------------
__global__ __launch_bounds__(256, 2)
void gemm1_kernel(const float* __restrict__ bias) {
    constexpr int KB = 6;
    constexpr uint32_t A_S  = 0;
    constexpr uint32_t B_S  = ABLK64;              // 18432
    constexpr uint32_t SBUF = ABLK64 + BBLK64;     // 55296
    constexpr uint32_t MB   = 2 * SBUF;            // 110592

    extern __shared__ char smem[];
    const uint32_t sb = smem_to_u32(smem);

    const int tid = threadIdx.x, warp = tid >> 5, lane = tid & 31;
    const int bi = blockIdx.x;
    const int nbase = blockIdx.y * 256;
    const int wm = (warp & 1) * 64;
    const int wn = (warp >> 1) * 64;

    const char* Abase = (const char*)g_x  + (size_t)bi * 6 * ABLK64;
    const char* Bbase = (const char*)g_w1 + (size_t)blockIdx.y * 6 * BBLK64;
    char* Obase = (char*)g_h1 + (size_t)bi * 8 * ABLK64;

    if (tid == 0) {
        MBARRIER_INIT(sb + MB, 1);
        MBARRIER_INIT(sb + MB + 8, 1);
    }
    __syncthreads();
    if (tid == 0) {
        MBARRIER_EXPECT_TX(sb + MB, SBUF);
        bulk_g2s(sb + A_S, Abase, ABLK64, sb + MB);
        bulk_g2s(sb + B_S, Bbase, BBLK64, sb + MB);
    }

    float acc[4][8][4];
#pragma unroll
    for (int mt = 0; mt < 4; mt++)
#pragma unroll
        for (int t = 0; t < 8; t++)
#pragma unroll
            for (int j = 0; j < 4; j++) acc[mt][t][j] = 0.f;

    const uint32_t a_off = (uint32_t)(wm + (lane & 15)) * 144 + ((lane >> 4) * 16);
    const uint32_t b_off = (uint32_t)(wn + (lane & 7) + ((lane >> 4) << 3)) * 144
                           + (((lane >> 3) & 1) * 16);

    for (int kb = 0; kb < KB; kb++) {
        __syncthreads();
        if (tid == 0 && kb + 1 < KB) {
            const uint32_t nb = sb + (uint32_t)((kb + 1) & 1) * SBUF;
            const uint32_t nm = sb + MB + ((kb + 1) & 1) * 8;
            MBARRIER_EXPECT_TX(nm, SBUF);
            bulk_g2s(nb + A_S, Abase + (size_t)(kb + 1) * ABLK64, ABLK64, nm);
            bulk_g2s(nb + B_S, Bbase + (size_t)(kb + 1) * BBLK64, BBLK64, nm);
        }
        MBARRIER_WAIT_PARITY(sb + MB + (kb & 1) * 8, (kb >> 1) & 1);

        const uint32_t bb = sb + (uint32_t)(kb & 1) * SBUF;
#pragma unroll
        for (int ks = 0; ks < 4; ks++) {
            uint32_t ah[4][4];
#pragma unroll
            for (int mt = 0; mt < 4; mt++)
                ldsm4(ah[mt], bb + A_S + a_off + mt * (16 * 144) + ks * 32);
#pragma unroll
            for (int t = 0; t < 4; t++) {
                uint32_t bh[4];
                ldsm4(bh, bb + B_S + b_off + t * (16 * 144) + ks * 32);
#pragma unroll
                for (int mt = 0; mt < 4; mt++) {
                    mma16816(acc[mt][2 * t],     ah[mt], bh);
                    mma16816(acc[mt][2 * t + 1], ah[mt], bh + 2);
                }
            }
        }
    }

    // epilogue -> h1 64-K 144-layout blocks
#pragma unroll
    for (int mt = 0; mt < 4; mt++) {
        const int rl0 = wm + mt * 16 + (lane >> 2);
        const int rl1 = rl0 + 8;
#pragma unroll
        for (int t = 0; t < 8; t++) {
            const int ncol = wn + t * 8 + (lane & 3) * 2;
            const float b0 = bias[nbase + ncol];
            const float b1 = bias[nbase + ncol + 1];
            float d0 = fmaxf(acc[mt][t][0] + b0, 0.f);
            float d1 = fmaxf(acc[mt][t][1] + b1, 0.f);
            float d2 = fmaxf(acc[mt][t][2] + b0, 0.f);
            float d3 = fmaxf(acc[mt][t][3] + b1, 0.f);
            const int ncg = nbase + ncol;
            char* blk = Obase + (size_t)(ncg >> 6) * ABLK64 + (ncg & 63) * 2;
            *(uint32_t*)(blk + rl0 * 144) = pack_h2(__float2half_rn(d0), __float2half_rn(d1));
            *(uint32_t*)(blk + rl1 * 144) = pack_h2(__float2half_rn(d2), __float2half_rn(d3));
        }
    }
}

// ---------------- megatail (round-15 structure) ----------------------------
__global__ __launch_bounds__(256, 1)
void megatail_kernel(const float* __restrict__ b2,
                     const float* __restrict__ b3,
                     const float* __restrict__ bc1,
                     const float* __restrict__ Wc2, const float* __restrict__ bc2,
                     const float* __restrict__ Wc3, const float* __restrict__ bc3,
                     float* __restrict__ out) {
    constexpr uint32_t A_S  = 0;
    constexpr uint32_t B_S  = ABLK64;
    constexpr uint32_t SBUF = ABLK64 + BBLK64;     // 55296
    constexpr uint32_t H2   = 110592;
    constexpr uint32_t COMB = 0;
    constexpr uint32_t WC1  = 43008;
    constexpr uint32_t WC2S = 64512;
    constexpr uint32_t WC3S = 72704;
    constexpr uint32_t W3S  = 73728;
    constexpr uint32_t MB   = 180224;
    constexpr int LDH = 336;

    extern __shared__ char smem[];
    const uint32_t sb = smem_to_u32(smem);
    float* smf = (float*)smem;

    const int tid = threadIdx.x, warp = tid >> 5, lane = tid & 31;
    const int bi = blockIdx.x;
    const int row0 = bi * 128;
    const int wm = (warp & 1) * 64;
    const int wn = (warp >> 1) * 64;

    if (tid == 0) {
        MBARRIER_INIT(sb + MB, 1);
        MBARRIER_INIT(sb + MB + 8, 1);
        MBARRIER_INIT(sb + MB + 16, 1);
    }
    __syncthreads();

    const char* Abase = (const char*)g_h1 + (size_t)bi * 8 * ABLK64;
    if (tid == 0) {
        MBARRIER_EXPECT_TX(sb + MB, SBUF);
        bulk_g2s(sb + A_S, Abase, ABLK64, sb + MB);
        bulk_g2s(sb + B_S, (const char*)g_w2, BBLK64, sb + MB);
    }

    // ---- gemm2: M128 x N256, 8 chunks of 64-K, 64x64 warp tiles ----
    const uint32_t a_off2 = (uint32_t)(wm + (lane & 15)) * 144 + ((lane >> 4) * 16);
    const uint32_t b_off2 = (uint32_t)(wn + (lane & 7) + ((lane >> 4) << 3)) * 144
                            + (((lane >> 3) & 1) * 16);

    float acc[4][8][4];
#pragma unroll
    for (int mt = 0; mt < 4; mt++)
#pragma unroll
        for (int t = 0; t < 8; t++)
#pragma unroll
            for (int j = 0; j < 4; j++) acc[mt][t][j] = 0.f;

    for (int kb = 0; kb < 8; kb++) {
        __syncthreads();
        if (tid == 0 && kb + 1 < 8) {
            const uint32_t nb = sb + (uint32_t)((kb + 1) & 1) * SBUF;
            const uint32_t nm = sb + MB + ((kb + 1) & 1) * 8;
            MBARRIER_EXPECT_TX(nm, SBUF);
            bulk_g2s(nb + A_S, Abase + (size_t)(kb + 1) * ABLK64, ABLK64, nm);
            bulk_g2s(nb + B_S, (const char*)g_w2 + (size_t)(kb + 1) * BBLK64,
                     BBLK64, nm);
        }
        MBARRIER_WAIT_PARITY(sb + MB + (kb & 1) * 8, (kb >> 1) & 1);

        const uint32_t bb = sb + (uint32_t)(kb & 1) * SBUF;
#pragma unroll
        for (int ks = 0; ks < 4; ks++) {
            uint32_t ah[4][4];
#pragma unroll
            for (int mt = 0; mt < 4; mt++)
                ldsm4(ah[mt], bb + A_S + a_off2 + mt * (16 * 144) + ks * 32);
#pragma unroll
            for (int t = 0; t < 4; t++) {
                uint32_t bh[4];
                ldsm4(bh, bb + B_S + b_off2 + t * (16 * 144) + ks * 32);
#pragma unroll
                for (int mt = 0; mt < 4; mt++) {
                    mma16816(acc[mt][2 * t],     ah[mt], bh);
                    mma16816(acc[mt][2 * t + 1], ah[mt], bh + 2);
                }
            }
        }
    }

    // gemm2 epilogue -> h2 smem (272-layout)
#pragma unroll
    for (int mt = 0; mt < 4; mt++) {
        const int r0 = wm + mt * 16 + (lane >> 2);
        const int r1 = r0 + 8;
#pragma unroll
        for (int t = 0; t < 8; t++) {
            const int ncg = wn + t * 8 + (lane & 3) * 2;
            const float c0 = b2[ncg], c1 = b2[ncg + 1];
            float d0 = fmaxf(acc[mt][t][0] + c0, 0.f);
            float d1 = fmaxf(acc[mt][t][1] + c1, 0.f);
            float d2 = fmaxf(acc[mt][t][2] + c0, 0.f);
            float d3 = fmaxf(acc[mt][t][3] + c1, 0.f);
            char* blk = smem + H2 + (ncg >> 7) * ABLK + (ncg & 127) * 2;
            *(uint32_t*)(blk + r0 * 272) = pack_h2(__float2half_rn(d0), __float2half_rn(d1));
            *(uint32_t*)(blk + r1 * 272) = pack_h2(__float2half_rn(d2), __float2half_rn(d3));
        }
    }
    __syncthreads();

    // head constants + statproj into P; w3 block 0 via bulk
    if (tid == 0) {
        MBARRIER_EXPECT_TX(sb + MB + 16, ABLK);
        bulk_g2s(sb + W3S, (const char*)g_w3, ABLK, sb + MB + 16);
    }
    for (int i = tid; i < 1280; i += 256) {
        int r = i / 20, g = i % 20;
        cp_async16(sb + WC1 + r * LDH + g * 16, g_wc1t + r * 160 + g * 8);
    }
    for (int i = tid; i < 512; i += 256) {
        const int r = i >> 2, g = i & 3;
        cp_async16(sb + COMB + r * LDH + 256 + g * 16,
                   g_statproj + (size_t)(row0 + r) * 32 + g * 8);
    }
    for (int i = tid; i < 512; i += 256)
        cp_async16(sb + WC2S + i * 16, Wc2 + i * 4);
    if (tid < 8) cp_async16(sb + WC3S + tid * 16, Wc3 + tid * 4);
    CP_COMMIT();

    // ---- gemm3: h2(smem) @ w3 streamed ----
    const int wn3 = (warp >> 1) * 32;
    float acc3[4][4][4];
#pragma unroll
    for (int mt = 0; mt < 4; mt++)
#pragma unroll
        for (int t = 0; t < 4; t++)
#pragma unroll
            for (int j = 0; j < 4; j++) acc3[mt][t][j] = 0.f;

    const uint32_t a_off3 = (uint32_t)(wm + (lane & 15)) * 272 + ((lane >> 4) * 16);
    const uint32_t b_off3 = (uint32_t)(wn3 + (lane & 7) + ((lane >> 4) << 3)) * 272
                            + (((lane >> 3) & 1) * 16);

    for (int kb = 0; kb < 2; kb++) {
        MBARRIER_WAIT_PARITY(sb + MB + 16, kb & 1);
        const uint32_t Ab = sb + H2 + kb * ABLK;
#pragma unroll
        for (int ks = 0; ks < 8; ks++) {
            uint32_t ah[4][4];
#pragma unroll
            for (int mt = 0; mt < 4; mt++)
                ldsm4(ah[mt], Ab + a_off3 + mt * (16 * 272) + ks * 32);
#pragma unroll
            for (int t = 0; t < 2; t++) {
                uint32_t bh[4];
                ldsm4(bh, sb + W3S + b_off3 + t * (16 * 272) + ks * 32);
#pragma unroll
                for (int mt = 0; mt < 4; mt++) {
                    mma16816(acc3[mt][2 * t],     ah[mt], bh);
                    mma16816(acc3[mt][2 * t + 1], ah[mt], bh + 2);
                }
            }
        }
        if (kb == 0) {
            __syncthreads();
            if (tid == 0) {
                MBARRIER_EXPECT_TX(sb + MB + 16, ABLK);
                bulk_g2s(sb + W3S, (const char*)g_w3 + ABLK, ABLK, sb + MB + 16);
            }
        }
    }

    // gemm3 epilogue -> comb cols [0,128)
    {
        char* combh = smem + COMB;
#pragma unroll
        for (int mt = 0; mt < 4; mt++) {
            const int r0 = wm + mt * 16 + (lane >> 2);
            const int r1 = r0 + 8;
#pragma unroll
            for (int t = 0; t < 4; t++) {
                const int ncol = wn3 + t * 8 + (lane & 3) * 2;
                const float c0 = b3[ncol], c1 = b3[ncol + 1];
                float d0 = fmaxf(acc3[mt][t][0] + c0, 0.f);
                float d1 = fmaxf(acc3[mt][t][1] + c1, 0.f);
                float d2 = fmaxf(acc3[mt][t][2] + c0, 0.f);
                float d3 = fmaxf(acc3[mt][t][3] + c1, 0.f);
                *(uint32_t*)(combh + r0 * LDH + ncol * 2) =
                    pack_h2(__float2half_rn(d0), __float2half_rn(d1));
                *(uint32_t*)(combh + r1 * LDH + ncol * 2) =
                    pack_h2(__float2half_rn(d2), __float2half_rn(d3));
            }
        }
    }
    CP_WAIT(0);
    __syncthreads();

    // ---- C1: comb[128,160] @ Wc1T[64,160]; warp grid 2m x 4n ----
    const int wnh = (warp >> 1) * 16;
    float acch[4][2][4];
#pragma unroll
    for (int mt = 0; mt < 4; mt++)
#pragma unroll
        for (int t = 0; t < 2; t++)
#pragma unroll
            for (int j = 0; j < 4; j++) acch[mt][t][j] = 0.f;

    const uint32_t a_offh = (uint32_t)(wm + (lane & 15)) * LDH + ((lane >> 4) * 16);
    const uint32_t b_offh = (uint32_t)(wnh + (lane & 7) + ((lane >> 4) << 3)) * LDH
                            + (((lane >> 3) & 1) * 16);
#pragma unroll
    for (int ks = 0; ks < 10; ks++) {
        uint32_t ah[4][4];
#pragma unroll
        for (int mt = 0; mt < 4; mt++)
            ldsm4(ah[mt], sb + COMB + a_offh + mt * (16 * LDH) + ks * 32);
        uint32_t bh[4];
        ldsm4(bh, sb + WC1 + b_offh + ks * 32);
#pragma unroll
        for (int mt = 0; mt < 4; mt++) {
            mma16816(acch[mt][0], ah[mt], bh);
            mma16816(acch[mt][1], ah[mt], bh + 2);
        }
    }
    __syncthreads();      // all warps done reading w3 smem
    float* c1s = smf + W3S / 4;
#pragma unroll
    for (int mt = 0; mt < 4; mt++) {
        const int r0 = wm + mt * 16 + (lane >> 2);
        const int r1 = r0 + 8;
#pragma unroll
        for (int t = 0; t < 2; t++) {
            const int ncol = wnh + t * 8 + (lane & 3) * 2;
            const float c0 = bc1[ncol], c1 = bc1[ncol + 1];
            c1s[r0 * 65 + ncol]     = fmaxf(acch[mt][t][0] + c0, 0.f);
            c1s[r0 * 65 + ncol + 1] = fmaxf(acch[mt][t][1] + c1, 0.f);
            c1s[r1 * 65 + ncol]     = fmaxf(acch[mt][t][2] + c0, 0.f);
            c1s[r1 * 65 + ncol + 1] = fmaxf(acch[mt][t][3] + c1, 0.f);
        }
    }
    __syncthreads();

    // ---- C2: [128,64]@[64,32] fp32 ----
    float* wc2s = smf + WC2S / 4;
    float* c2s  = smf + H2 / 4;
    {
        const int r = tid >> 1;
        const int j0 = (tid & 1) * 16;
        float a[16];
#pragma unroll
        for (int j = 0; j < 16; j++) a[j] = bc2[j0 + j];
        const float* c1r = c1s + r * 65;
        for (int k = 0; k < 64; k++) {
            const float v = c1r[k];
            const float* w = wc2s + k * 32 + j0;
#pragma unroll
            for (int j = 0; j < 16; j++) a[j] += v * w[j];
        }
        float* c2r = c2s + r * 33;
#pragma unroll
        for (int j = 0; j < 16; j++) c2r[j0 + j] = fmaxf(a[j], 0.f);
    }
    __syncthreads();

    // ---- C3 + sigmoid ----
    if (tid < 128) {
        const float* c2r = c2s + tid * 33;
        const float* w3 = smf + WC3S / 4;
        float z = bc3[0];
#pragma unroll
        for (int k = 0; k < 32; k++) z += c2r[k] * w3[k];
        out[row0 + tid] = 1.0f / (1.0f + expf(-z));
    }
}

// ---------------- launch ---------------------------------------------------
extern "C" void kernel_launch(void* const* d_in, const int* in_sizes, int n_in,
                              void* d_out, int out_size) {
    const float* x   = (const float*)d_in[0];
    const float* W1  = (const float*)d_in[1];
    const float* b1  = (const float*)d_in[2];
    const float* W2  = (const float*)d_in[3];
    const float* b2  = (const float*)d_in[4];
    const float* W3  = (const float*)d_in[5];
    const float* b3  = (const float*)d_in[6];
    const float* Ws  = (const float*)d_in[7];
    const float* bs  = (const float*)d_in[8];
    const float* Wc1 = (const float*)d_in[9];
    const float* bc1 = (const float*)d_in[10];
    const float* Wc2 = (const float*)d_in[11];
    const float* bc2 = (const float*)d_in[12];
    const float* Wc3 = (const float*)d_in[13];
    const float* bc3 = (const float*)d_in[14];
    float* out = (float*)d_out;

    const int SMEM_G1 = 110592 + 32;        // 110624 -> 2 CTAs/SM
    const int SMEM_MT = 180224 + 32;

    static bool attr_set = false;
    if (!attr_set) {
        cudaFuncSetAttribute(gemm1_kernel,
                             cudaFuncAttributeMaxDynamicSharedMemorySize, SMEM_G1);
        cudaFuncSetAttribute(megatail_kernel,
                             cudaFuncAttributeMaxDynamicSharedMemorySize, SMEM_MT);
        attr_set = true;
    }

    prep_kernel<<<XB_BLOCKS + WB_BLOCKS, 256>>>(x, Ws, bs, W1, W2, W3, Wc1);

    dim3 g1(MTOT / 128, 2);
    gemm1_kernel<<<g1, 256, SMEM_G1>>>(b1);
    megatail_kernel<<<MTOT / 128, 256, SMEM_MT>>>(b2, b3, bc1, Wc2, bc2,
                                                  Wc3, bc3, out);
}

// round 17
// speedup vs baseline: 1.6738x; 1.6738x over previous
#include <cuda_runtime.h>
#include <cuda_fp16.h>
#include <math.h>
#include <cstdint>

// ===========================================================================
// Fused MLP on HMMA fp16 (hard dispatch rate 512 MAC/cyc/SM), bulk-copy
// staged; operands stored in gmem as exact padded smem tile images.
//   prep    : merged — x fp32 -> fp16 272-layout A-blocks + stats proj;
//             W1 -> 272 B-blocks; W2 -> 144 64-K blocks; W3 -> 272 blocks;
//             Wc1 -> transposed fp16
//   gemm1   : h1 = relu(x@W1+b1), K-chunk 128, 1 CTA/SM (round-15 champion)
//   megatail: full-width gemm2 -> smem h2 -> gemm3 (w3 streamed) -> C1 ->
//             C2/C3 -> sigmoid
// ===========================================================================

#define MTOT 65536
#define ABLK 34816u      // 128 rows x 272B
#define BBLK2 69632u     // 256 rows x 272B
#define ABLK64 18432u    // 128 rows x 144B
#define BBLK64 36864u    // 256 rows x 144B

// ---------------- device scratch -------------------------------------------
__device__ __half g_x [(size_t)512 * 3 * 17408];
__device__ __half g_w1[(size_t)2 * 3 * 34816];
__device__ __half g_w2[(size_t)8 * 18432];        // [kb(8)] 256 rows x 144B
__device__ __half g_w3[(size_t)2 * 17408];
__device__ __half g_h1[(size_t)512 * 8 * 9216];   // per-tile 8 x 64-K (144)
__device__ __half g_wc1t[64 * 160];
__device__ __half g_statproj[(size_t)MTOT * 32];

// ---------------- helpers --------------------------------------------------
__device__ __forceinline__ uint32_t smem_to_u32(const void* p) {
    uint32_t a;
    asm("{ .reg .u64 t; cvta.to.shared.u64 t, %1; cvt.u32.u64 %0, t; }"
        : "=r"(a) : "l"(p));
    return a;
}
__device__ __forceinline__ void ldsm4(uint32_t* r, uint32_t addr) {
    asm volatile("ldmatrix.sync.aligned.m8n8.x4.shared.b16 {%0,%1,%2,%3}, [%4];"
        : "=r"(r[0]), "=r"(r[1]), "=r"(r[2]), "=r"(r[3]) : "r"(addr));
}
__device__ __forceinline__ void mma16816(float* c, const uint32_t* a,
                                         const uint32_t* b) {
    asm volatile(
        "mma.sync.aligned.m16n8k16.row.col.f32.f16.f16.f32 "
        "{%0,%1,%2,%3}, {%4,%5,%6,%7}, {%8,%9}, {%0,%1,%2,%3};"
        : "+f"(c[0]), "+f"(c[1]), "+f"(c[2]), "+f"(c[3])
        : "r"(a[0]), "r"(a[1]), "r"(a[2]), "r"(a[3]), "r"(b[0]), "r"(b[1]));
}
__device__ __forceinline__ void cp_async16(uint32_t dst, const void* src) {
    asm volatile("cp.async.cg.shared.global [%0], [%1], 16;"
        :: "r"(dst), "l"(src));
}
#define CP_COMMIT() asm volatile("cp.async.commit_group;" ::: "memory")
#define CP_WAIT(n)  asm volatile("cp.async.wait_group %0;" :: "n"(n) : "memory")

__device__ __forceinline__ void bulk_g2s(uint32_t dst, const void* src,
                                         uint32_t bytes, uint32_t mbar) {
    asm volatile(
        "cp.async.bulk.shared::cta.global.mbarrier::complete_tx::bytes "
        "[%0], [%1], %2, [%3];"
        :: "r"(dst), "l"(src), "r"(bytes), "r"(mbar) : "memory");
}
#define MBARRIER_INIT(mbar, cnt) \
    asm volatile("mbarrier.init.shared.b64 [%0], %1;" \
        :: "r"((uint32_t)(mbar)), "r"((uint32_t)(cnt)) : "memory")
#define MBARRIER_EXPECT_TX(mbar, bytes) \
    asm volatile("mbarrier.arrive.expect_tx.shared.b64 _, [%0], %1;" \
        :: "r"((uint32_t)(mbar)), "r"((uint32_t)(bytes)) : "memory")
#define MBARRIER_WAIT_PARITY(mbar, par) do { \
    uint32_t _m = (uint32_t)(mbar); uint32_t _p = (uint32_t)(par); uint32_t _d; \
    asm volatile("{\n\t.reg .pred p;\n\t" \
        "mbarrier.try_wait.parity.acquire.cta.shared::cta.b64 p, [%1], %2;\n\t" \
        "selp.b32 %0, 1, 0, p;\n\t}" : "=r"(_d) : "r"(_m), "r"(_p) : "memory"); \
    if (!_d) { \
        asm volatile("{\n\t.reg .pred P1;\n\t" \
            "WAIT_LOOP_%=:\n\t" \
            "mbarrier.try_wait.parity.acquire.cta.shared::cta.b64 P1, [%0], %1, 0x989680;\n\t" \
            "@P1 bra.uni WAIT_DONE_%=;\n\t" \
            "bra.uni WAIT_LOOP_%=;\n\t" \
            "WAIT_DONE_%=:\n\t}" :: "r"(_m), "r"(_p) : "memory"); \
    } \
} while (0)

__device__ __forceinline__ uint32_t pack_h2(__half a, __half b) {
    __half2 t; t.x = a; t.y = b;
    return *(uint32_t*)&t;
}

// ---------------- merged prep (x role + w role by blockIdx) ----------------
#define XB_BLOCKS (MTOT / 8)                  // 8192
#define W1T_ELEMS (512 * 384)
#define W2T_ELEMS (256 * 512)
#define W3T_ELEMS (128 * 256)
#define WC1T_ELEMS (64 * 160)
#define WT_TOTAL  (W1T_ELEMS + W2T_ELEMS + W3T_ELEMS + WC1T_ELEMS)
#define WB_BLOCKS ((WT_TOTAL + 255) / 256)

__global__ __launch_bounds__(256)
void prep_kernel(const float* __restrict__ x,
                 const float* __restrict__ Ws, const float* __restrict__ bs,
                 const float* __restrict__ W1, const float* __restrict__ W2,
                 const float* __restrict__ W3, const float* __restrict__ Wc1) {
    if (blockIdx.x < XB_BLOCKS) {
        // ---- x role ----
        const int warp = threadIdx.x >> 5, lane = threadIdx.x & 31;
        const int r = blockIdx.x * 8 + warp;
        const float* xr = x + (size_t)r * 365;

        float v[12];
        float s = 0.f, mn = 3.4e38f, mx = -3.4e38f;
#pragma unroll
        for (int i = 0; i < 12; i++) {
            int k = lane + 32 * i;
            bool ok = k < 365;
            v[i] = ok ? xr[k] : 0.f;
            if (ok) { s += v[i]; mn = fminf(mn, v[i]); mx = fmaxf(mx, v[i]); }
        }
#pragma unroll
        for (int o = 16; o; o >>= 1) {
            s += __shfl_xor_sync(0xffffffffu, s, o);
            mn = fminf(mn, __shfl_xor_sync(0xffffffffu, mn, o));
            mx = fmaxf(mx, __shfl_xor_sync(0xffffffffu, mx, o));
        }
        const float mu = s * (1.0f / 365.0f);
        float s2 = 0.f, s3 = 0.f, s4 = 0.f;
#pragma unroll
        for (int i = 0; i < 12; i++) {
            int k = lane + 32 * i;
            if (k < 365) {
                float c = v[i] - mu, c2 = c * c;
                s2 += c2; s3 += c2 * c; s4 += c2 * c2;
            }
        }
#pragma unroll
        for (int o = 16; o; o >>= 1) {
            s2 += __shfl_xor_sync(0xffffffffu, s2, o);
            s3 += __shfl_xor_sync(0xffffffffu, s3, o);
            s4 += __shfl_xor_sync(0xffffffffu, s4, o);
        }
        const float var1 = s2 * (1.0f / 364.0f);
        const float sig = sqrtf(var1);
        const float m3 = s3 * (1.0f / 365.0f);
        const float m4 = s4 * (1.0f / 365.0f);
        const float sig2 = sig * sig;
        const float skew = m3 / (sig * sig2 + 1e-8f);
        const float kurt = m4 / (sig2 * sig2 + 1e-8f);

        {
            const int j = lane;
            float a = bs[j];
            a += mu   * Ws[0 * 32 + j];
            a += sig  * Ws[1 * 32 + j];
            a += mn   * Ws[2 * 32 + j];
            a += mx   * Ws[3 * 32 + j];
            a += skew * Ws[4 * 32 + j];
            a += kurt * Ws[5 * 32 + j];
            g_statproj[(size_t)r * 32 + j] = __float2half_rn(a);
        }
        const int mt = r >> 7, rl = r & 127;
#pragma unroll
        for (int i = 0; i < 12; i++) {
            int k = lane + 32 * i;
            float val = (k < 365) ? v[i] : 0.f;
            const int kb = k >> 7, kl = k & 127;
            g_x[((size_t)(mt * 3 + kb)) * 17408 + rl * 136 + kl] = __float2half_rn(val);
        }
    } else {
        // ---- w role ----
        int idx = (blockIdx.x - XB_BLOCKS) * 256 + threadIdx.x;
        if (idx >= WT_TOTAL) return;
        if (idx < W1T_ELEMS) {
            int n = idx / 384, k = idx % 384;
            float v = (k < 365) ? W1[(size_t)k * 512 + n] : 0.f;
            int pass = n >> 8, nl = n & 255, kb = k >> 7, kl = k & 127;
            g_w1[((size_t)(pass * 3 + kb)) * 34816 + nl * 136 + kl] = __float2half_rn(v);
        } else if (idx < W1T_ELEMS + W2T_ELEMS) {
            int j = idx - W1T_ELEMS;
            int n = j / 512, k = j % 512;
            int kb = k >> 6, kl = k & 63;
            g_w2[(size_t)kb * 18432 + n * 72 + kl] =
                __float2half_rn(W2[(size_t)k * 256 + n]);
        } else if (idx < W1T_ELEMS + W2T_ELEMS + W3T_ELEMS) {
            int j = idx - W1T_ELEMS - W2T_ELEMS;
            int n = j / 256, k = j % 256;
            int kb = k >> 7, kl = k & 127;
            g_w3[(size_t)kb * 17408 + n * 136 + kl] =
                __float2half_rn(W3[(size_t)k * 128 + n]);
        } else {
            int j = idx - W1T_ELEMS - W2T_ELEMS - W3T_ELEMS;
            int n = j / 160, k = j % 160;
            g_wc1t[j] = __float2half_rn(Wc1[(size_t)k * 64 + n]);
        }
    }
}

// ---------------- gemm1: x@W1 -> h1 (144-layout out), round-15 config ------
__global__ __launch_bounds__(256, 1)
void gemm1_kernel(const float* __restrict__ bias) {
    constexpr int KB    = 3;
    constexpr int LDSB  = 272;
    constexpr uint32_t A_S  = 0;
    constexpr uint32_t B_S  = ABLK;
    constexpr uint32_t SBUF = ABLK + BBLK2;
    constexpr uint32_t MB   = 2 * SBUF;

    extern __shared__ char smem[];
    const uint32_t sb = smem_to_u32(smem);

    const int tid = threadIdx.x, warp = tid >> 5, lane = tid & 31;
    const int bi = blockIdx.x;
    const int nbase = blockIdx.y * 256;
    const int wm = (warp & 1) * 64;
    const int wn = (warp >> 1) * 64;

    const char* Abase = (const char*)g_x  + (size_t)bi * 3 * ABLK;
    const char* Bbase = (const char*)g_w1 + (size_t)blockIdx.y * 3 * BBLK2;
    char* Obase = (char*)g_h1 + (size_t)bi * 8 * ABLK64;

    if (tid == 0) {
        MBARRIER_INIT(sb + MB, 1);
        MBARRIER_INIT(sb + MB + 8, 1);
    }
    __syncthreads();
    if (tid == 0) {
        MBARRIER_EXPECT_TX(sb + MB, ABLK + BBLK2);
        bulk_g2s(sb + A_S, Abase, ABLK, sb + MB);
        bulk_g2s(sb + B_S, Bbase, BBLK2, sb + MB);
    }

    float acc[4][8][4];
#pragma unroll
    for (int mt = 0; mt < 4; mt++)
#pragma unroll
        for (int t = 0; t < 8; t++)
#pragma unroll
            for (int j = 0; j < 4; j++) acc[mt][t][j] = 0.f;

    const uint32_t a_off = (uint32_t)(wm + (lane & 15)) * LDSB + ((lane >> 4) * 16);
    const uint32_t b_off = (uint32_t)(wn + (lane & 7) + ((lane >> 4) << 3)) * LDSB
                           + (((lane >> 3) & 1) * 16);

    for (int kb = 0; kb < KB; kb++) {
        __syncthreads();
        if (tid == 0 && kb + 1 < KB) {
            const uint32_t nb = sb + (uint32_t)((kb + 1) & 1) * SBUF;
            const uint32_t nm = sb + MB + ((kb + 1) & 1) * 8;
            MBARRIER_EXPECT_TX(nm, ABLK + BBLK2);
            bulk_g2s(nb + A_S, Abase + (size_t)(kb + 1) * ABLK, ABLK, nm);
            bulk_g2s(nb + B_S, Bbase + (size_t)(kb + 1) * BBLK2, BBLK2, nm);
        }
        MBARRIER_WAIT_PARITY(sb + MB + (kb & 1) * 8, (kb >> 1) & 1);

        const uint32_t bb = sb + (uint32_t)(kb & 1) * SBUF;
#pragma unroll
        for (int ks = 0; ks < 8; ks++) {
            uint32_t ah[4][4];
#pragma unroll
            for (int mt = 0; mt < 4; mt++)
                ldsm4(ah[mt], bb + A_S + a_off + mt * (16 * LDSB) + ks * 32);
#pragma unroll
            for (int t = 0; t < 4; t++) {
                uint32_t bh[4];
                ldsm4(bh, bb + B_S + b_off + t * (16 * LDSB) + ks * 32);
#pragma unroll
                for (int mt = 0; mt < 4; mt++) {
                    mma16816(acc[mt][2 * t],     ah[mt], bh);
                    mma16816(acc[mt][2 * t + 1], ah[mt], bh + 2);
                }
            }
        }
    }

#pragma unroll
    for (int mt = 0; mt < 4; mt++) {
        const int rl0 = wm + mt * 16 + (lane >> 2);
        const int rl1 = rl0 + 8;
#pragma unroll
        for (int t = 0; t < 8; t++) {
            const int ncol = wn + t * 8 + (lane & 3) * 2;
            const float b0 = bias[nbase + ncol];
            const float b1 = bias[nbase + ncol + 1];
            float d0 = fmaxf(acc[mt][t][0] + b0, 0.f);
            float d1 = fmaxf(acc[mt][t][1] + b1, 0.f);
            float d2 = fmaxf(acc[mt][t][2] + b0, 0.f);
            float d3 = fmaxf(acc[mt][t][3] + b1, 0.f);
            const int ncg = nbase + ncol;
            char* blk = Obase + (size_t)(ncg >> 6) * ABLK64 + (ncg & 63) * 2;
            *(uint32_t*)(blk + rl0 * 144) = pack_h2(__float2half_rn(d0), __float2half_rn(d1));
            *(uint32_t*)(blk + rl1 * 144) = pack_h2(__float2half_rn(d2), __float2half_rn(d3));
        }
    }
}

// ---------------- megatail (round-15 structure) ----------------------------
__global__ __launch_bounds__(256, 1)
void megatail_kernel(const float* __restrict__ b2,
                     const float* __restrict__ b3,
                     const float* __restrict__ bc1,
                     const float* __restrict__ Wc2, const float* __restrict__ bc2,
                     const float* __restrict__ Wc3, const float* __restrict__ bc3,
                     float* __restrict__ out) {
    constexpr uint32_t A_S  = 0;
    constexpr uint32_t B_S  = ABLK64;
    constexpr uint32_t SBUF = ABLK64 + BBLK64;     // 55296
    constexpr uint32_t H2   = 110592;
    constexpr uint32_t COMB = 0;
    constexpr uint32_t WC1  = 43008;
    constexpr uint32_t WC2S = 64512;
    constexpr uint32_t WC3S = 72704;
    constexpr uint32_t W3S  = 73728;
    constexpr uint32_t MB   = 180224;
    constexpr int LDH = 336;

    extern __shared__ char smem[];
    const uint32_t sb = smem_to_u32(smem);
    float* smf = (float*)smem;

    const int tid = threadIdx.x, warp = tid >> 5, lane = tid & 31;
    const int bi = blockIdx.x;
    const int row0 = bi * 128;
    const int wm = (warp & 1) * 64;
    const int wn = (warp >> 1) * 64;

    if (tid == 0) {
        MBARRIER_INIT(sb + MB, 1);
        MBARRIER_INIT(sb + MB + 8, 1);
        MBARRIER_INIT(sb + MB + 16, 1);
    }
    __syncthreads();

    const char* Abase = (const char*)g_h1 + (size_t)bi * 8 * ABLK64;
    if (tid == 0) {
        MBARRIER_EXPECT_TX(sb + MB, SBUF);
        bulk_g2s(sb + A_S, Abase, ABLK64, sb + MB);
        bulk_g2s(sb + B_S, (const char*)g_w2, BBLK64, sb + MB);
    }

    // ---- gemm2: M128 x N256, 8 chunks of 64-K, 64x64 warp tiles ----
    const uint32_t a_off2 = (uint32_t)(wm + (lane & 15)) * 144 + ((lane >> 4) * 16);
    const uint32_t b_off2 = (uint32_t)(wn + (lane & 7) + ((lane >> 4) << 3)) * 144
                            + (((lane >> 3) & 1) * 16);

    float acc[4][8][4];
#pragma unroll
    for (int mt = 0; mt < 4; mt++)
#pragma unroll
        for (int t = 0; t < 8; t++)
#pragma unroll
            for (int j = 0; j < 4; j++) acc[mt][t][j] = 0.f;

    for (int kb = 0; kb < 8; kb++) {
        __syncthreads();
        if (tid == 0 && kb + 1 < 8) {
            const uint32_t nb = sb + (uint32_t)((kb + 1) & 1) * SBUF;
            const uint32_t nm = sb + MB + ((kb + 1) & 1) * 8;
            MBARRIER_EXPECT_TX(nm, SBUF);
            bulk_g2s(nb + A_S, Abase + (size_t)(kb + 1) * ABLK64, ABLK64, nm);
            bulk_g2s(nb + B_S, (const char*)g_w2 + (size_t)(kb + 1) * BBLK64,
                     BBLK64, nm);
        }
        MBARRIER_WAIT_PARITY(sb + MB + (kb & 1) * 8, (kb >> 1) & 1);

        const uint32_t bb = sb + (uint32_t)(kb & 1) * SBUF;
#pragma unroll
        for (int ks = 0; ks < 4; ks++) {
            uint32_t ah[4][4];
#pragma unroll
            for (int mt = 0; mt < 4; mt++)
                ldsm4(ah[mt], bb + A_S + a_off2 + mt * (16 * 144) + ks * 32);
#pragma unroll
            for (int t = 0; t < 4; t++) {
                uint32_t bh[4];
                ldsm4(bh, bb + B_S + b_off2 + t * (16 * 144) + ks * 32);
#pragma unroll
                for (int mt = 0; mt < 4; mt++) {
                    mma16816(acc[mt][2 * t],     ah[mt], bh);
                    mma16816(acc[mt][2 * t + 1], ah[mt], bh + 2);
                }
            }
        }
    }

    // gemm2 epilogue -> h2 smem (272-layout)
#pragma unroll
    for (int mt = 0; mt < 4; mt++) {
        const int r0 = wm + mt * 16 + (lane >> 2);
        const int r1 = r0 + 8;
#pragma unroll
        for (int t = 0; t < 8; t++) {
            const int ncg = wn + t * 8 + (lane & 3) * 2;
            const float c0 = b2[ncg], c1 = b2[ncg + 1];
            float d0 = fmaxf(acc[mt][t][0] + c0, 0.f);
            float d1 = fmaxf(acc[mt][t][1] + c1, 0.f);
            float d2 = fmaxf(acc[mt][t][2] + c0, 0.f);
            float d3 = fmaxf(acc[mt][t][3] + c1, 0.f);
            char* blk = smem + H2 + (ncg >> 7) * ABLK + (ncg & 127) * 2;
            *(uint32_t*)(blk + r0 * 272) = pack_h2(__float2half_rn(d0), __float2half_rn(d1));
            *(uint32_t*)(blk + r1 * 272) = pack_h2(__float2half_rn(d2), __float2half_rn(d3));
        }
    }
    __syncthreads();

    // head constants + statproj into P; w3 block 0 via bulk
    if (tid == 0) {
        MBARRIER_EXPECT_TX(sb + MB + 16, ABLK);
        bulk_g2s(sb + W3S, (const char*)g_w3, ABLK, sb + MB + 16);
    }
    for (int i = tid; i < 1280; i += 256) {
        int r = i / 20, g = i % 20;
        cp_async16(sb + WC1 + r * LDH + g * 16, g_wc1t + r * 160 + g * 8);
    }
    for (int i = tid; i < 512; i += 256) {
        const int r = i >> 2, g = i & 3;
        cp_async16(sb + COMB + r * LDH + 256 + g * 16,
                   g_statproj + (size_t)(row0 + r) * 32 + g * 8);
    }
    for (int i = tid; i < 512; i += 256)
        cp_async16(sb + WC2S + i * 16, Wc2 + i * 4);
    if (tid < 8) cp_async16(sb + WC3S + tid * 16, Wc3 + tid * 4);
    CP_COMMIT();

    // ---- gemm3: h2(smem) @ w3 streamed ----
    const int wn3 = (warp >> 1) * 32;
    float acc3[4][4][4];
#pragma unroll
    for (int mt = 0; mt < 4; mt++)
#pragma unroll
        for (int t = 0; t < 4; t++)
#pragma unroll
            for (int j = 0; j < 4; j++) acc3[mt][t][j] = 0.f;

    const uint32_t a_off3 = (uint32_t)(wm + (lane & 15)) * 272 + ((lane >> 4) * 16);
    const uint32_t b_off3 = (uint32_t)(wn3 + (lane & 7) + ((lane >> 4) << 3)) * 272
                            + (((lane >> 3) & 1) * 16);

    for (int kb = 0; kb < 2; kb++) {
        MBARRIER_WAIT_PARITY(sb + MB + 16, kb & 1);
        const uint32_t Ab = sb + H2 + kb * ABLK;
#pragma unroll
        for (int ks = 0; ks < 8; ks++) {
            uint32_t ah[4][4];
#pragma unroll
            for (int mt = 0; mt < 4; mt++)
                ldsm4(ah[mt], Ab + a_off3 + mt * (16 * 272) + ks * 32);
#pragma unroll
            for (int t = 0; t < 2; t++) {
                uint32_t bh[4];
                ldsm4(bh, sb + W3S + b_off3 + t * (16 * 272) + ks * 32);
#pragma unroll
                for (int mt = 0; mt < 4; mt++) {
                    mma16816(acc3[mt][2 * t],     ah[mt], bh);
                    mma16816(acc3[mt][2 * t + 1], ah[mt], bh + 2);
                }
            }
        }
        if (kb == 0) {
            __syncthreads();
            if (tid == 0) {
                MBARRIER_EXPECT_TX(sb + MB + 16, ABLK);
                bulk_g2s(sb + W3S, (const char*)g_w3 + ABLK, ABLK, sb + MB + 16);
            }
        }
    }

    // gemm3 epilogue -> comb cols [0,128)
    {
        char* combh = smem + COMB;
#pragma unroll
        for (int mt = 0; mt < 4; mt++) {
            const int r0 = wm + mt * 16 + (lane >> 2);
            const int r1 = r0 + 8;
#pragma unroll
            for (int t = 0; t < 4; t++) {
                const int ncol = wn3 + t * 8 + (lane & 3) * 2;
                const float c0 = b3[ncol], c1 = b3[ncol + 1];
                float d0 = fmaxf(acc3[mt][t][0] + c0, 0.f);
                float d1 = fmaxf(acc3[mt][t][1] + c1, 0.f);
                float d2 = fmaxf(acc3[mt][t][2] + c0, 0.f);
                float d3 = fmaxf(acc3[mt][t][3] + c1, 0.f);
                *(uint32_t*)(combh + r0 * LDH + ncol * 2) =
                    pack_h2(__float2half_rn(d0), __float2half_rn(d1));
                *(uint32_t*)(combh + r1 * LDH + ncol * 2) =
                    pack_h2(__float2half_rn(d2), __float2half_rn(d3));
            }
        }
    }
    CP_WAIT(0);
    __syncthreads();

    // ---- C1: comb[128,160] @ Wc1T[64,160]; warp grid 2m x 4n ----
    const int wnh = (warp >> 1) * 16;
    float acch[4][2][4];
#pragma unroll
    for (int mt = 0; mt < 4; mt++)
#pragma unroll
        for (int t = 0; t < 2; t++)
#pragma unroll
            for (int j = 0; j < 4; j++) acch[mt][t][j] = 0.f;

    const uint32_t a_offh = (uint32_t)(wm + (lane & 15)) * LDH + ((lane >> 4) * 16);
    const uint32_t b_offh = (uint32_t)(wnh + (lane & 7) + ((lane >> 4) << 3)) * LDH
                            + (((lane >> 3) & 1) * 16);
#pragma unroll
    for (int ks = 0; ks < 10; ks++) {
        uint32_t ah[4][4];
#pragma unroll
        for (int mt = 0; mt < 4; mt++)
            ldsm4(ah[mt], sb + COMB + a_offh + mt * (16 * LDH) + ks * 32);
        uint32_t bh[4];
        ldsm4(bh, sb + WC1 + b_offh + ks * 32);
#pragma unroll
        for (int mt = 0; mt < 4; mt++) {
            mma16816(acch[mt][0], ah[mt], bh);
            mma16816(acch[mt][1], ah[mt], bh + 2);
        }
    }
    __syncthreads();      // all warps done reading w3 smem
    float* c1s = smf + W3S / 4;
#pragma unroll
    for (int mt = 0; mt < 4; mt++) {
        const int r0 = wm + mt * 16 + (lane >> 2);
        const int r1 = r0 + 8;
#pragma unroll
        for (int t = 0; t < 2; t++) {
            const int ncol = wnh + t * 8 + (lane & 3) * 2;
            const float c0 = bc1[ncol], c1 = bc1[ncol + 1];
            c1s[r0 * 65 + ncol]     = fmaxf(acch[mt][t][0] + c0, 0.f);
            c1s[r0 * 65 + ncol + 1] = fmaxf(acch[mt][t][1] + c1, 0.f);
            c1s[r1 * 65 + ncol]     = fmaxf(acch[mt][t][2] + c0, 0.f);
            c1s[r1 * 65 + ncol + 1] = fmaxf(acch[mt][t][3] + c1, 0.f);
        }
    }
    __syncthreads();

    // ---- C2: [128,64]@[64,32] fp32 ----
    float* wc2s = smf + WC2S / 4;
    float* c2s  = smf + H2 / 4;
    {
        const int r = tid >> 1;
        const int j0 = (tid & 1) * 16;
        float a[16];
#pragma unroll
        for (int j = 0; j < 16; j++) a[j] = bc2[j0 + j];
        const float* c1r = c1s + r * 65;
        for (int k = 0; k < 64; k++) {
            const float v = c1r[k];
            const float* w = wc2s + k * 32 + j0;
#pragma unroll
            for (int j = 0; j < 16; j++) a[j] += v * w[j];
        }
        float* c2r = c2s + r * 33;
#pragma unroll
        for (int j = 0; j < 16; j++) c2r[j0 + j] = fmaxf(a[j], 0.f);
    }
    __syncthreads();

    // ---- C3 + sigmoid ----
    if (tid < 128) {
        const float* c2r = c2s + tid * 33;
        const float* w3 = smf + WC3S / 4;
        float z = bc3[0];
#pragma unroll
        for (int k = 0; k < 32; k++) z += c2r[k] * w3[k];
        out[row0 + tid] = 1.0f / (1.0f + expf(-z));
    }
}

// ---------------- launch ---------------------------------------------------
extern "C" void kernel_launch(void* const* d_in, const int* in_sizes, int n_in,
                              void* d_out, int out_size) {
    const float* x   = (const float*)d_in[0];
    const float* W1  = (const float*)d_in[1];
    const float* b1  = (const float*)d_in[2];
    const float* W2  = (const float*)d_in[3];
    const float* b2  = (const float*)d_in[4];
    const float* W3  = (const float*)d_in[5];
    const float* b3  = (const float*)d_in[6];
    const float* Ws  = (const float*)d_in[7];
    const float* bs  = (const float*)d_in[8];
    const float* Wc1 = (const float*)d_in[9];
    const float* bc1 = (const float*)d_in[10];
    const float* Wc2 = (const float*)d_in[11];
    const float* bc2 = (const float*)d_in[12];
    const float* Wc3 = (const float*)d_in[13];
    const float* bc3 = (const float*)d_in[14];
    float* out = (float*)d_out;

    const int SMEM_G1 = 2 * 104448 + 32;    // 208928, 1 CTA/SM, regs free
    const int SMEM_MT = 180224 + 32;

    static bool attr_set = false;
    if (!attr_set) {
        cudaFuncSetAttribute(gemm1_kernel,
                             cudaFuncAttributeMaxDynamicSharedMemorySize, SMEM_G1);
        cudaFuncSetAttribute(megatail_kernel,
                             cudaFuncAttributeMaxDynamicSharedMemorySize, SMEM_MT);
        attr_set = true;
    }

    prep_kernel<<<XB_BLOCKS + WB_BLOCKS, 256>>>(x, Ws, bs, W1, W2, W3, Wc1);

    dim3 g1(MTOT / 128, 2);
    gemm1_kernel<<<g1, 256, SMEM_G1>>>(b1);
    megatail_kernel<<<MTOT / 128, 256, SMEM_MT>>>(b2, b3, bc1, Wc2, bc2,
                                                  Wc3, bc3, out);
}